// round 11
// baseline (speedup 1.0000x reference)
#include <cuda_runtime.h>
#include <cuda_fp16.h>
#include <cstdint>
#include <cstddef>

#define NN 16384
#define DD 512
#define WPR 256   // half2 words per row (DD/2)
#define NSEG 16   // column-topk row segments

// ---------------- scratch (device globals; sanctioned) ------------------------
__device__ float    g_simT[(size_t)NN * NN]; // simT[i][j] = <R_i, L_j>
__device__ uint32_t g_Lhi[(size_t)NN * WPR];
__device__ uint32_t g_Llo[(size_t)NN * WPR];
__device__ uint32_t g_Rhi[(size_t)NN * WPR];
__device__ float    g_part[NSEG][NN][10];    // per-segment column top-10
__device__ float    g_RL[NN];
__device__ float    g_P [NN];

// ---------------- precompute: fp16 hi/lo split, packed half2 ------------------
__global__ __launch_bounds__(256)
void cvt_hl(const float* __restrict__ L, const float* __restrict__ R) {
    const size_t w = (size_t)blockIdx.x * 256 + threadIdx.x;
    if (blockIdx.y == 0) {
        float2 v = ((const float2*)L)[w];
        __half hx = __float2half_rn(v.x);
        __half hy = __float2half_rn(v.y);
        float lx = v.x - __half2float(hx);
        float ly = v.y - __half2float(hy);
        __half2 hhi = __halves2half2(hx, hy);
        __half2 hlo = __floats2half2_rn(lx, ly);
        g_Lhi[w] = *(uint32_t*)&hhi;
        g_Llo[w] = *(uint32_t*)&hlo;
    } else {
        float2 v = ((const float2*)R)[w];
        __half2 hhi = __floats2half2_rn(v.x, v.y);
        g_Rhi[w] = *(uint32_t*)&hhi;
    }
}

// ---------------- fp16 MMA + ldmatrix ----------------------------------------
__device__ __forceinline__ void mma_f16(float* c, const uint32_t* a, uint32_t b0, uint32_t b1) {
    asm volatile(
        "mma.sync.aligned.m16n8k16.row.col.f32.f16.f16.f32 "
        "{%0,%1,%2,%3}, {%4,%5,%6,%7}, {%8,%9}, {%0,%1,%2,%3};"
        : "+f"(c[0]), "+f"(c[1]), "+f"(c[2]), "+f"(c[3])
        : "r"(a[0]), "r"(a[1]), "r"(a[2]), "r"(a[3]), "r"(b0), "r"(b1));
}

__device__ __forceinline__ void ldsm4(uint32_t* r, uint32_t addr) {
    asm volatile("ldmatrix.sync.aligned.m8n8.x4.shared.b16 {%0,%1,%2,%3}, [%4];"
                 : "=r"(r[0]), "=r"(r[1]), "=r"(r[2]), "=r"(r[3]) : "r"(addr));
}

// ---------------- GEMM: simT = R . L^T  (2-term fp16 split) -------------------
// C = Ahi*Bhi + Ahi*Blo.  BM=BN=128, chunk=16 k, double-buffered, 36KB smem.
#define BM 128
#define BN 128
#define SSTW 12      // padded words per smem row (48B: conflict-free for ldmatrix)
#define CSZ (128 * SSTW)

__global__ __launch_bounds__(256, 2)
void gemm_hl() {
    __shared__ uint32_t S[2][3][CSZ];   // [buf][Ahi,Bhi,Blo]

    const int bm = blockIdx.y * BM;     // rows of R
    const int bn = blockIdx.x * BN;     // rows of L
    const int tid  = threadIdx.x;
    const int warp = tid >> 5;
    const int lane = tid & 31;
    const int wm = (warp & 3) * 32;     // warp tile 32(m) x 64(n)
    const int wn = (warp >> 2) * 64;

    const int l_row = tid >> 1;
    const int l_wb  = (tid & 1) * 4;

    const uint4* gAhi = (const uint4*)g_Rhi;   // A = R
    const uint4* gBhi = (const uint4*)g_Lhi;   // B = L
    const uint4* gBlo = (const uint4*)g_Llo;

    uint4 pa_h, pb_h, pb_l;
    auto load_regs = [&](int c) {
        size_t ia = ((size_t)(bm + l_row) * WPR + c * 8 + l_wb) >> 2;
        size_t ib = ((size_t)(bn + l_row) * WPR + c * 8 + l_wb) >> 2;
        pa_h = gAhi[ia];
        pb_h = gBhi[ib]; pb_l = gBlo[ib];
    };
    auto store_smem = [&](int buf) {
        int off = l_row * SSTW + l_wb;
        *(uint4*)&S[buf][0][off] = pa_h;
        *(uint4*)&S[buf][1][off] = pb_h;
        *(uint4*)&S[buf][2][off] = pb_l;
    };

    const uint32_t sb = (uint32_t)__cvta_generic_to_shared(&S[0][0][0]);
    const uint32_t aW = (uint32_t)((wm + (lane & 15)) * SSTW + ((lane >> 4) << 2));
    const uint32_t bW = (uint32_t)((wn + (lane & 7) + ((lane >> 4) << 3)) * SSTW +
                                   (((lane >> 3) & 1) << 2));

    float acc[2][8][4];
#pragma unroll
    for (int im = 0; im < 2; im++)
#pragma unroll
        for (int in = 0; in < 8; in++)
#pragma unroll
            for (int q = 0; q < 4; q++) acc[im][in][q] = 0.0f;

    load_regs(0);
    store_smem(0);
    __syncthreads();

    const int NCHUNK = DD / 16;   // 32
    for (int c = 0; c < NCHUNK; c++) {
        if (c + 1 < NCHUNK) load_regs(c + 1);

        const uint32_t bufoff = (uint32_t)((c & 1) * 3 * CSZ);
        const uint32_t aHiA = sb + (bufoff + 0 * CSZ + aW) * 4;
        const uint32_t bHiA = sb + (bufoff + 1 * CSZ + bW) * 4;
        const uint32_t bLoA = sb + (bufoff + 2 * CSZ + bW) * 4;

        uint32_t afh[2][4];
#pragma unroll
        for (int im = 0; im < 2; im++)
            ldsm4(afh[im], aHiA + im * 16 * SSTW * 4);

#pragma unroll
        for (int inp = 0; inp < 4; inp++) {
            uint32_t bh[4], bl[4];
            ldsm4(bh, bHiA + inp * 16 * SSTW * 4);
            ldsm4(bl, bLoA + inp * 16 * SSTW * 4);
#pragma unroll
            for (int s = 0; s < 2; s++) {
                const int in = inp * 2 + s;
#pragma unroll
                for (int im = 0; im < 2; im++) {
                    mma_f16(acc[im][in], afh[im], bh[2 * s], bh[2 * s + 1]);  // hi*hi
                    mma_f16(acc[im][in], afh[im], bl[2 * s], bl[2 * s + 1]);  // hi*lo
                }
            }
        }

        if (c + 1 < NCHUNK) store_smem((c + 1) & 1);
        __syncthreads();
    }

    // epilogue
#pragma unroll
    for (int im = 0; im < 2; im++) {
#pragma unroll
        for (int in = 0; in < 8; in++) {
            int m = bm + wm + im * 16 + (lane >> 2);
            int n = bn + wn + in * 8 + 2 * (lane & 3);
            *(float2*)&g_simT[(size_t)m * NN + n]       = make_float2(acc[im][in][0], acc[im][in][1]);
            *(float2*)&g_simT[(size_t)(m + 8) * NN + n] = make_float2(acc[im][in][2], acc[im][in][3]);
        }
    }
}

// ---------------- top-10 insertion (t ascending; t[0] = current min) ----------
__device__ __forceinline__ void insert10(float* t, float v) {
    if (v > t[0]) {
        t[0] = v;
#pragma unroll
        for (int i = 0; i < 9; i++) {
            if (t[i] > t[i + 1]) { float tmp = t[i]; t[i] = t[i + 1]; t[i + 1] = tmp; }
        }
    }
}

#define SENT (-1e30f)

// ---------------- RL: per-row top-10 mean of simT (max-screened) --------------
__global__ __launch_bounds__(256)
void row_topk_mean() {
    __shared__ float s[256 * 10];
    const int row = blockIdx.x;
    const int tid = threadIdx.x;
    const float4* p = (const float4*)(g_simT + (size_t)row * NN);

    float t[10];
#pragma unroll
    for (int i = 0; i < 10; i++) t[i] = SENT;

    for (int j = tid; j < NN / 4; j += 256) {
        float4 v = p[j];
        float m = fmaxf(fmaxf(v.x, v.y), fmaxf(v.z, v.w));
        if (m > t[0]) {
            insert10(t, v.x); insert10(t, v.y); insert10(t, v.z); insert10(t, v.w);
        }
    }
#pragma unroll
    for (int i = 0; i < 10; i++) s[tid * 10 + i] = t[i];
    __syncthreads();

    if (tid < 32) {
#pragma unroll
        for (int i = 0; i < 10; i++) t[i] = s[tid * 10 + i];
        for (int src = tid + 32; src < 256; src += 32) {
            if (s[src * 10 + 9] > t[0])   // segment max vs current min
#pragma unroll
                for (int i = 0; i < 10; i++) insert10(t, s[src * 10 + i]);
        }
#pragma unroll
        for (int i = 0; i < 10; i++) s[tid * 10 + i] = t[i];
    }
    __syncthreads();

    if (tid == 0) {
#pragma unroll
        for (int i = 0; i < 10; i++) t[i] = s[i];
        for (int src = 1; src < 32; src++) {
            if (s[src * 10 + 9] > t[0])
#pragma unroll
                for (int i = 0; i < 10; i++) insert10(t, s[src * 10 + i]);
        }
        float sum = 0.0f;
#pragma unroll
        for (int i = 0; i < 10; i++) sum += t[i];
        g_RL[row] = sum * 0.1f;
    }
}

// ---------------- LR stage 1: per-segment column top-10 (max-screened) --------
__global__ __launch_bounds__(256)
void col_topk_part() {
    const int col = blockIdx.x * 256 + threadIdx.x;
    const int seg = blockIdx.y;

    float t[10];
#pragma unroll
    for (int i = 0; i < 10; i++) t[i] = SENT;

    const float* base = g_simT + (size_t)seg * (NN / NSEG) * NN + col;
#pragma unroll 1
    for (int r = 0; r < NN / NSEG; r += 8) {
        float v0 = base[(size_t)(r + 0) * NN];
        float v1 = base[(size_t)(r + 1) * NN];
        float v2 = base[(size_t)(r + 2) * NN];
        float v3 = base[(size_t)(r + 3) * NN];
        float v4 = base[(size_t)(r + 4) * NN];
        float v5 = base[(size_t)(r + 5) * NN];
        float v6 = base[(size_t)(r + 6) * NN];
        float v7 = base[(size_t)(r + 7) * NN];
        float m = fmaxf(fmaxf(fmaxf(v0, v1), fmaxf(v2, v3)),
                        fmaxf(fmaxf(v4, v5), fmaxf(v6, v7)));
        if (m > t[0]) {
            insert10(t, v0); insert10(t, v1); insert10(t, v2); insert10(t, v3);
            insert10(t, v4); insert10(t, v5); insert10(t, v6); insert10(t, v7);
        }
    }
#pragma unroll
    for (int i = 0; i < 10; i++) g_part[seg][col][i] = t[i];
}

// ---------------- LR stage 2: merge segments; P = LR + RL ---------------------
__global__ __launch_bounds__(256)
void col_topk_reduce() {
    const int col = blockIdx.x * 256 + threadIdx.x;
    float t[10];
#pragma unroll
    for (int i = 0; i < 10; i++) t[i] = g_part[0][col][i];
#pragma unroll
    for (int seg = 1; seg < NSEG; seg++)
#pragma unroll
        for (int i = 0; i < 10; i++) insert10(t, g_part[seg][col][i]);
    float sum = 0.0f;
#pragma unroll
    for (int i = 0; i < 10; i++) sum += t[i];
    g_P[col] = sum * 0.1f + g_RL[col];   // P = LR + RL (RL ready: row kernel ran)
}

// ---------------- rank + top1 over csls rows ---------------------------------
// csls[i][j] = 2*simT[i][j] - P[j]; rank = #gt + #eq(j<i); ranks as FLOAT.
__global__ __launch_bounds__(256)
void rank_top1(float* __restrict__ ranks, float* __restrict__ top1) {
    __shared__ int   s_gt[256];
    __shared__ int   s_eq[256];
    __shared__ float s_mx[256];

    const int i   = blockIdx.x;
    const int tid = threadIdx.x;
    const float* prow = g_simT + (size_t)i * NN;
    const float d = 2.0f * prow[i] - g_P[i];

    int cnt_gt = 0, cnt_eq = 0;
    float mx = SENT;

    const float4* pv = (const float4*)prow;
    const float4* qv = (const float4*)g_P;
    for (int j4 = tid; j4 < NN / 4; j4 += 256) {
        float4 v = pv[j4];
        float4 q = qv[j4];
        int j = j4 * 4;
        float c0 = 2.0f * v.x - q.x;
        float c1 = 2.0f * v.y - q.y;
        float c2 = 2.0f * v.z - q.z;
        float c3 = 2.0f * v.w - q.w;
        cnt_gt += (c0 > d) + (c1 > d) + (c2 > d) + (c3 > d);
        if (c0 == d && (j + 0) < i) cnt_eq++;
        if (c1 == d && (j + 1) < i) cnt_eq++;
        if (c2 == d && (j + 2) < i) cnt_eq++;
        if (c3 == d && (j + 3) < i) cnt_eq++;
        mx = fmaxf(mx, fmaxf(fmaxf(c0, c1), fmaxf(c2, c3)));
    }

    s_gt[tid] = cnt_gt; s_eq[tid] = cnt_eq; s_mx[tid] = mx;
    __syncthreads();
    for (int str = 128; str > 0; str >>= 1) {
        if (tid < str) {
            s_gt[tid] += s_gt[tid + str];
            s_eq[tid] += s_eq[tid + str];
            s_mx[tid] = fmaxf(s_mx[tid], s_mx[tid + str]);
        }
        __syncthreads();
    }
    if (tid == 0) {
        ranks[i] = (float)(s_gt[0] + s_eq[0]);
        top1[i]  = s_mx[0];
    }
}

// ---------------- launch ------------------------------------------------------
extern "C" void kernel_launch(void* const* d_in, const int* in_sizes, int n_in,
                              void* d_out, int out_size) {
    const float* L = (const float*)d_in[0];
    const float* R = (const float*)d_in[1];

    dim3 cgrid(NN * WPR / 256, 2);
    cvt_hl<<<cgrid, 256>>>(L, R);

    dim3 grid(NN / BN, NN / BM);
    gemm_hl<<<grid, 256>>>();

    row_topk_mean<<<NN, 256>>>();                    // RL over simT rows
    col_topk_part<<<dim3(NN / 256, NSEG), 256>>>();  // LR stage 1
    col_topk_reduce<<<NN / 256, 256>>>();            // LR stage 2 + P

    float* ranks = (float*)d_out;
    float* top1  = (float*)d_out + NN;
    rank_top1<<<NN, 256>>>(ranks, top1);
}